// round 8
// baseline (speedup 1.0000x reference)
#include <cuda_runtime.h>
#include <cuda_bf16.h>
#include <stdint.h>

// ===========================================================================
// MoE-LoRA fused linear:  y = x @ W + (1/R) * (x @ A[l]) @ B[l] + bias
//   x: [T,D] f32, labels: [T] i32/i64, W: [D,D] f32, A: [E,D,R] f32,
//   B: [E,R,D] f32, bias: [D] f32, out: [T,D] f32.  T=16384 D=1024 R=8 E=64
//
// bf16-split GEMM on tensor cores: x@W = x_hi@W_hi + x_hi@W_lo + x_lo@W_hi
// Round 8: SAME structure as round 7, but the inner loop issues MMAs
// term-major so consecutive MMAs target DISTINCT accumulators (dependency
// distance 8 instead of 1). Round 7's 3 back-to-back MMAs on one accumulator
// serialized the tensor pipe at 39%.
// ===========================================================================

#define D_DIM 1024
#define R_DIM 8
#define SCALING 0.125f
#define MAX_T 16384

#define BM 128
#define BN 128
#define BKB 32                        // bf16 K per chunk (per plane)
#define NSTAGE 3
#define NCHUNK 32                     // 1024 / 32
#define ROWSTRIDE 40                  // bf16 per smem row (32 + 8 pad) = 80 B
#define PLANE_BYTES (128 * ROWSTRIDE * 2)     // 10240
#define OFF_XH 0
#define OFF_XL (PLANE_BYTES)
#define OFF_WH (2 * PLANE_BYTES)
#define OFF_WL (3 * PLANE_BYTES)
#define STAGE_BYTES (4 * PLANE_BYTES)         // 40960
#define SMEM_BYTES (NSTAGE * STAGE_BYTES)     // 122880

// -------------------- device-global scratch (no allocs allowed) ------------
__device__ __align__(256) unsigned short g_x_hi[MAX_T * D_DIM];
__device__ __align__(256) unsigned short g_x_lo[MAX_T * D_DIM];
__device__ __align__(256) unsigned short g_w_hi[D_DIM * D_DIM];  // W^T hi
__device__ __align__(256) unsigned short g_w_lo[D_DIM * D_DIM];  // W^T lo
__device__ __align__(16)  float          g_xa[MAX_T * R_DIM];
__device__ int g_lab64;

// ------------------------------ helpers ------------------------------------
__device__ __forceinline__ uint32_t smem_u32(const void* p) {
    uint32_t a;
    asm("{ .reg .u64 t; cvta.to.shared.u64 t, %1; cvt.u32.u64 %0, t; }"
        : "=r"(a) : "l"(p));
    return a;
}
#define CP_ASYNC16(dst, src) \
    asm volatile("cp.async.cg.shared.global [%0], [%1], 16;" \
                 :: "r"(dst), "l"(src) : "memory")
#define CP_COMMIT() asm volatile("cp.async.commit_group;" ::: "memory")
#define CP_WAIT1()  asm volatile("cp.async.wait_group 1;" ::: "memory")
#define CP_WAIT0()  asm volatile("cp.async.wait_group 0;" ::: "memory")

#define LDSM4(r0, r1, r2, r3, addr) \
    asm volatile("ldmatrix.sync.aligned.m8n8.x4.shared.b16 {%0,%1,%2,%3}, [%4];" \
                 : "=r"(r0), "=r"(r1), "=r"(r2), "=r"(r3) : "r"(addr))

#define MMA16816(c, a, b) \
    asm volatile("mma.sync.aligned.m16n8k16.row.col.f32.bf16.bf16.f32 " \
                 "{%0,%1,%2,%3}, {%4,%5,%6,%7}, {%8,%9}, {%0,%1,%2,%3};" \
                 : "+f"((c)[0]), "+f"((c)[1]), "+f"((c)[2]), "+f"((c)[3]) \
                 : "r"((a)[0]), "r"((a)[1]), "r"((a)[2]), "r"((a)[3]), \
                   "r"((b)[0]), "r"((b)[1]))

// ---------------------------------------------------------------------------
// Kernel 0: classify labels dtype (int64 vs int32) deterministically.
// ---------------------------------------------------------------------------
__global__ void detect_label_dtype_kernel(const void* labels, int T) {
    if (threadIdx.x != 0 || blockIdx.x != 0) return;
    const long long* p = (const long long*)labels;
    int n = T < 256 ? T : 256;
    int is64 = 1;
    for (int i = 0; i < n; ++i) {
        long long v = p[i];
        if (v < 0 || v >= (1LL << 31)) { is64 = 0; break; }
    }
    g_lab64 = is64;
}
__device__ __forceinline__ int load_label(const void* labels, int t) {
    if (g_lab64) return (int)((const long long*)labels)[t];
    return ((const int*)labels)[t];
}

// ---------------------------------------------------------------------------
// Kernel 1: fused  x -> (x_hi, x_lo) bf16 split  +  xa = x . A[label]
// ---------------------------------------------------------------------------
__global__ void __launch_bounds__(256)
convert_x_xa_kernel(const float* __restrict__ x,
                    const void*  __restrict__ labels,
                    const float* __restrict__ A, int T) {
    int t = blockIdx.x * 8 + (threadIdx.x >> 5);
    if (t >= T) return;
    const int lane = threadIdx.x & 31;
    const int e = load_label(labels, t);
    const float* xrow = x + (size_t)t * D_DIM;
    const float* Ae   = A + (size_t)e * D_DIM * R_DIM;
    unsigned short* xh = g_x_hi + (size_t)t * D_DIM;
    unsigned short* xl = g_x_lo + (size_t)t * D_DIM;

    float acc[R_DIM];
#pragma unroll
    for (int r = 0; r < R_DIM; ++r) acc[r] = 0.0f;

#pragma unroll
    for (int i = 0; i < 8; ++i) {
        const int d = i * 128 + lane * 4;
        float4 v = *(const float4*)(xrow + d);

        ushort4 hi, lo;
        float vv[4] = {v.x, v.y, v.z, v.w};
        unsigned short hb[4], lb[4];
#pragma unroll
        for (int j = 0; j < 4; ++j) {
            __nv_bfloat16 h = __float2bfloat16_rn(vv[j]);
            __nv_bfloat16 l = __float2bfloat16_rn(vv[j] - __bfloat162float(h));
            hb[j] = *(unsigned short*)&h;
            lb[j] = *(unsigned short*)&l;
        }
        hi.x = hb[0]; hi.y = hb[1]; hi.z = hb[2]; hi.w = hb[3];
        lo.x = lb[0]; lo.y = lb[1]; lo.z = lb[2]; lo.w = lb[3];
        *(ushort4*)(xh + d) = hi;
        *(ushort4*)(xl + d) = lo;

#pragma unroll
        for (int j = 0; j < 4; ++j) {
            const float4* ap = (const float4*)(Ae + (size_t)(d + j) * R_DIM);
            float4 a0 = ap[0], a1 = ap[1];
            float xv = vv[j];
            acc[0] += xv * a0.x;  acc[1] += xv * a0.y;
            acc[2] += xv * a0.z;  acc[3] += xv * a0.w;
            acc[4] += xv * a1.x;  acc[5] += xv * a1.y;
            acc[6] += xv * a1.z;  acc[7] += xv * a1.w;
        }
    }
#pragma unroll
    for (int off = 16; off > 0; off >>= 1)
#pragma unroll
        for (int r = 0; r < R_DIM; ++r)
            acc[r] += __shfl_down_sync(0xffffffffu, acc[r], off);
    if (lane == 0) {
        float4* o = (float4*)(g_xa + (size_t)t * R_DIM);
        o[0] = make_float4(acc[0], acc[1], acc[2], acc[3]);
        o[1] = make_float4(acc[4], acc[5], acc[6], acc[7]);
    }
}

// ---------------------------------------------------------------------------
// Kernel 2: Wt[n][k] = W[k][n], split into bf16 hi/lo planes.
// ---------------------------------------------------------------------------
__global__ void __launch_bounds__(256)
convert_w_kernel(const float* __restrict__ W) {
    __shared__ float s[32][33];
    const int k0 = blockIdx.x * 32;
    const int n0 = blockIdx.y * 32;
    const int tx = threadIdx.x & 31;
    const int ty = threadIdx.x >> 5;
#pragma unroll
    for (int r = 0; r < 4; ++r) {
        int kk = ty + r * 8;
        s[kk][tx] = W[(size_t)(k0 + kk) * D_DIM + n0 + tx];
    }
    __syncthreads();
#pragma unroll
    for (int r = 0; r < 4; ++r) {
        int nn = ty + r * 8;
        float v = s[tx][nn];
        __nv_bfloat16 h = __float2bfloat16_rn(v);
        __nv_bfloat16 l = __float2bfloat16_rn(v - __bfloat162float(h));
        size_t o = (size_t)(n0 + nn) * D_DIM + k0 + tx;
        g_w_hi[o] = *(unsigned short*)&h;
        g_w_lo[o] = *(unsigned short*)&l;
    }
}

// ---------------------------------------------------------------------------
// Kernel 3: plane-shared bf16x3 GEMM + fused LoRA/bias epilogue.
//   512 threads = 16 warps (4M x 4N), warp tile 32x32, BM=BN=128.
//   Term-major MMA issue: consecutive MMAs hit distinct accumulators.
// ---------------------------------------------------------------------------
__global__ void __launch_bounds__(512, 1)
gemm_lora_kernel(const void*  __restrict__ labels,
                 const float* __restrict__ Bmat,
                 const float* __restrict__ bias,
                 float* __restrict__ out) {
    extern __shared__ char smem[];
    const uint32_t sbase = smem_u32(smem);
    const int tid  = threadIdx.x;
    const int row0 = blockIdx.y * BM;
    const int col0 = blockIdx.x * BN;

    // cp.async geometry: 1 x 16B op per plane per thread
    const int lrow = tid >> 2;           // 0..127
    const int lseg = tid & 3;            // 16B segment within 64B row

    // warp/lane geometry: 4M x 4N warps, each 32x32
    const int warp = tid >> 5, lane = tid & 31;
    const int wm = warp >> 2, wn = warp & 3;
    const uint32_t a_lm_base =
        (uint32_t)((wm * 32 + (lane & 15)) * ROWSTRIDE + (lane >> 4) * 8) * 2;
    const uint32_t b_lm_base =
        (uint32_t)((wn * 32 + (lane >> 4) * 8 + (lane & 7)) * ROWSTRIDE +
                   ((lane >> 3) & 1) * 8) * 2;

    float c[2][4][4];
#pragma unroll
    for (int i = 0; i < 2; ++i)
#pragma unroll
        for (int j = 0; j < 4; ++j)
#pragma unroll
            for (int q = 0; q < 4; ++q) c[i][j][q] = 0.0f;

    auto issue = [&](int cn) {
        const int kk = cn * BKB;
        const uint32_t sa = sbase + (uint32_t)(cn % NSTAGE) * STAGE_BYTES;
        const uint32_t doff = (uint32_t)(lrow * (ROWSTRIDE * 2) + lseg * 16);
        const size_t gx = (size_t)(row0 + lrow) * D_DIM + kk + lseg * 8;
        const size_t gw = (size_t)(col0 + lrow) * D_DIM + kk + lseg * 8;
        CP_ASYNC16(sa + OFF_XH + doff, g_x_hi + gx);
        CP_ASYNC16(sa + OFF_XL + doff, g_x_lo + gx);
        CP_ASYNC16(sa + OFF_WH + doff, g_w_hi + gw);
        CP_ASYNC16(sa + OFF_WL + doff, g_w_lo + gw);
    };

    // prologue: fill 2 stages
    issue(0); CP_COMMIT();
    issue(1); CP_COMMIT();

    for (int ch = 0; ch < NCHUNK; ++ch) {
        CP_WAIT1();
        __syncthreads();
        const uint32_t sa = sbase + (uint32_t)(ch % NSTAGE) * STAGE_BYTES;

#pragma unroll
        for (int ks = 0; ks < 2; ++ks) {
            // resident B fragments (16 regs): both planes
            uint32_t bh[4][2], bl[4][2];
#pragma unroll
            for (int p = 0; p < 2; ++p) {
                uint32_t bo = b_lm_base + (uint32_t)(p * 16 * ROWSTRIDE + ks * 16) * 2;
                uint32_t r0, r1, r2, r3;
                LDSM4(r0, r1, r2, r3, sa + OFF_WH + bo);
                bh[2 * p][0] = r0;      bh[2 * p][1] = r1;
                bh[2 * p + 1][0] = r2;  bh[2 * p + 1][1] = r3;
                LDSM4(r0, r1, r2, r3, sa + OFF_WL + bo);
                bl[2 * p][0] = r0;      bl[2 * p][1] = r1;
                bl[2 * p + 1][0] = r2;  bl[2 * p + 1][1] = r3;
            }
            // resident A fragments (16 regs): both planes, both m-tiles
            uint32_t ah[2][4], al[2][4];
#pragma unroll
            for (int mf = 0; mf < 2; ++mf) {
                uint32_t ao = a_lm_base + (uint32_t)(mf * 16 * ROWSTRIDE + ks * 16) * 2;
                LDSM4(ah[mf][0], ah[mf][1], ah[mf][2], ah[mf][3], sa + OFF_XH + ao);
                LDSM4(al[mf][0], al[mf][1], al[mf][2], al[mf][3], sa + OFF_XL + ao);
            }
            // term-major issue: same accumulator recurs at distance 8
#pragma unroll
            for (int mf = 0; mf < 2; ++mf)
#pragma unroll
                for (int nf = 0; nf < 4; ++nf)
                    MMA16816(c[mf][nf], ah[mf], bh[nf]);
#pragma unroll
            for (int mf = 0; mf < 2; ++mf)
#pragma unroll
                for (int nf = 0; nf < 4; ++nf)
                    MMA16816(c[mf][nf], ah[mf], bl[nf]);
#pragma unroll
            for (int mf = 0; mf < 2; ++mf)
#pragma unroll
                for (int nf = 0; nf < 4; ++nf)
                    MMA16816(c[mf][nf], al[mf], bh[nf]);
        }

        if (ch + 2 < NCHUNK) { issue(ch + 2); }
        CP_COMMIT();
    }
    CP_WAIT0();
    __syncthreads();

    // ---- stage accumulators to smem (reuse pipeline smem) ----
    float* acc_s = (float*)smem;                 // [128][132]
    const int g = lane >> 2, q = lane & 3;
#pragma unroll
    for (int mf = 0; mf < 2; ++mf) {
        const int r1 = wm * 32 + mf * 16 + g;
#pragma unroll
        for (int nf = 0; nf < 4; ++nf) {
            const int cc = wn * 32 + nf * 8 + q * 2;
            *(float2*)&acc_s[r1 * 132 + cc]       = make_float2(c[mf][nf][0], c[mf][nf][1]);
            *(float2*)&acc_s[(r1 + 8) * 132 + cc] = make_float2(c[mf][nf][2], c[mf][nf][3]);
        }
    }
    __syncthreads();

    // ---- epilogue: per-token rank-8 LoRA + bias, vectorized ----
    const int lr   = tid >> 2;           // 0..127
    const int qcol = (tid & 3) * 32;     // 32-col quarter
    const int t    = row0 + lr;
    const int e    = load_label(labels, t);

    float xs[R_DIM];
    {
        const float4* p = (const float4*)(g_xa + (size_t)t * R_DIM);
        float4 a0 = p[0], a1 = p[1];
        xs[0] = SCALING * a0.x; xs[1] = SCALING * a0.y;
        xs[2] = SCALING * a0.z; xs[3] = SCALING * a0.w;
        xs[4] = SCALING * a1.x; xs[5] = SCALING * a1.y;
        xs[6] = SCALING * a1.z; xs[7] = SCALING * a1.w;
    }

    float res[32];
#pragma unroll
    for (int v = 0; v < 8; ++v)
        *(float4*)&res[v * 4] = *(const float4*)&acc_s[lr * 132 + qcol + v * 4];

    const float* Be = Bmat + (size_t)e * R_DIM * D_DIM + col0 + qcol;
#pragma unroll
    for (int r = 0; r < R_DIM; ++r) {
        const float4* bp = (const float4*)(Be + (size_t)r * D_DIM);
        const float xr = xs[r];
#pragma unroll
        for (int v = 0; v < 8; ++v) {
            float4 b4 = bp[v];
            res[v * 4 + 0] += xr * b4.x;
            res[v * 4 + 1] += xr * b4.y;
            res[v * 4 + 2] += xr * b4.z;
            res[v * 4 + 3] += xr * b4.w;
        }
    }
    const float4* bi = (const float4*)(bias + col0 + qcol);
    float* op = out + (size_t)t * D_DIM + col0 + qcol;
#pragma unroll
    for (int v = 0; v < 8; ++v) {
        float4 bv = bi[v];
        float4 o4 = make_float4(res[v * 4 + 0] + bv.x, res[v * 4 + 1] + bv.y,
                                res[v * 4 + 2] + bv.z, res[v * 4 + 3] + bv.w);
        ((float4*)op)[v] = o4;
    }
}

// ---------------------------------------------------------------------------
// kernel_launch — graph-capturable, allocation-free.
// Inputs: x, labels, W, A, B, bias
// ---------------------------------------------------------------------------
extern "C" void kernel_launch(void* const* d_in, const int* in_sizes, int n_in,
                              void* d_out, int out_size) {
    const float* x      = (const float*)d_in[0];
    const void*  labels = (const void*) d_in[1];
    const float* W      = (const float*)d_in[2];
    const float* A      = (const float*)d_in[3];
    const float* B      = (const float*)d_in[4];
    const float* bias   = (const float*)d_in[5];
    float* out          = (float*)d_out;

    const int T = in_sizes[0] / D_DIM;

    detect_label_dtype_kernel<<<1, 32>>>(labels, T);
    convert_x_xa_kernel<<<(T + 7) / 8, 256>>>(x, labels, A, T);
    convert_w_kernel<<<dim3(D_DIM / 32, D_DIM / 32), 256>>>(W);

    static int smem_set = 0;
    if (!smem_set) {
        cudaFuncSetAttribute(gemm_lora_kernel,
                             cudaFuncAttributeMaxDynamicSharedMemorySize, SMEM_BYTES);
        smem_set = 1;
    }
    dim3 grid(D_DIM / BN, T / BM);
    gemm_lora_kernel<<<grid, 512, SMEM_BYTES>>>(labels, B, bias, out);
}

// round 9
// speedup vs baseline: 1.4714x; 1.4714x over previous
#include <cuda_runtime.h>
#include <cuda_fp16.h>
#include <stdint.h>

// ===========================================================================
// MoE-LoRA fused linear:  y = x @ W + (1/R) * (x @ A[l]) @ B[l] + bias
//   x: [T,D] f32, labels: [T] i32/i64, W: [D,D] f32, A: [E,D,R] f32,
//   B: [E,R,D] f32, bias: [D] f32, out: [T,D] f32.  T=16384 D=1024 R=8 E=64
//
// Round 9: SINGLE-PASS fp16 GEMM (mma.sync m16n8k16 f32.f16.f16.f32).
// fp16's 10-bit mantissa gives ~4e-4 output rel err (< 1e-3 threshold),
// cutting MMA count 3x and operand traffic 2x vs the bf16x3 split.
// 5-stage cp.async pipeline, prefetch issued BEFORE compute (distance 4).
// ===========================================================================

#define D_DIM 1024
#define R_DIM 8
#define SCALING 0.125f
#define MAX_T 16384

#define BM 128
#define BN 128
#define BKB 64                        // fp16 K per chunk
#define NSTAGE 5
#define NCHUNK 16                     // 1024 / 64
#define ROWSTRIDE 72                  // fp16 per smem row (64 + 8 pad) = 144 B
#define PLANE_BYTES (128 * ROWSTRIDE * 2)     // 18432
#define OFF_X 0
#define OFF_W (PLANE_BYTES)
#define STAGE_BYTES (2 * PLANE_BYTES)         // 36864
#define SMEM_BYTES (NSTAGE * STAGE_BYTES)     // 184320

// -------------------- device-global scratch (no allocs allowed) ------------
__device__ __align__(256) unsigned short g_x16[MAX_T * D_DIM];   // x fp16
__device__ __align__(256) unsigned short g_w16[D_DIM * D_DIM];   // W^T fp16
__device__ __align__(16)  float          g_xa[MAX_T * R_DIM];
__device__ int g_lab64;

// ------------------------------ helpers ------------------------------------
__device__ __forceinline__ uint32_t smem_u32(const void* p) {
    uint32_t a;
    asm("{ .reg .u64 t; cvta.to.shared.u64 t, %1; cvt.u32.u64 %0, t; }"
        : "=r"(a) : "l"(p));
    return a;
}
#define CP_ASYNC16(dst, src) \
    asm volatile("cp.async.cg.shared.global [%0], [%1], 16;" \
                 :: "r"(dst), "l"(src) : "memory")
#define CP_COMMIT() asm volatile("cp.async.commit_group;" ::: "memory")
#define CP_WAIT3()  asm volatile("cp.async.wait_group 3;" ::: "memory")
#define CP_WAIT0()  asm volatile("cp.async.wait_group 0;" ::: "memory")

#define LDSM4(r0, r1, r2, r3, addr) \
    asm volatile("ldmatrix.sync.aligned.m8n8.x4.shared.b16 {%0,%1,%2,%3}, [%4];" \
                 : "=r"(r0), "=r"(r1), "=r"(r2), "=r"(r3) : "r"(addr))

#define MMA16816F16(c, a, b) \
    asm volatile("mma.sync.aligned.m16n8k16.row.col.f32.f16.f16.f32 " \
                 "{%0,%1,%2,%3}, {%4,%5,%6,%7}, {%8,%9}, {%0,%1,%2,%3};" \
                 : "+f"((c)[0]), "+f"((c)[1]), "+f"((c)[2]), "+f"((c)[3]) \
                 : "r"((a)[0]), "r"((a)[1]), "r"((a)[2]), "r"((a)[3]), \
                   "r"((b)[0]), "r"((b)[1]))

// ---------------------------------------------------------------------------
// Kernel 0: classify labels dtype (int64 vs int32) deterministically.
// ---------------------------------------------------------------------------
__global__ void detect_label_dtype_kernel(const void* labels, int T) {
    if (threadIdx.x != 0 || blockIdx.x != 0) return;
    const long long* p = (const long long*)labels;
    int n = T < 256 ? T : 256;
    int is64 = 1;
    for (int i = 0; i < n; ++i) {
        long long v = p[i];
        if (v < 0 || v >= (1LL << 31)) { is64 = 0; break; }
    }
    g_lab64 = is64;
}
__device__ __forceinline__ int load_label(const void* labels, int t) {
    if (g_lab64) return (int)((const long long*)labels)[t];
    return ((const int*)labels)[t];
}

// ---------------------------------------------------------------------------
// Kernel 1: fused  x -> fp16  +  xa = x . A[label]   (one warp per token)
// ---------------------------------------------------------------------------
__global__ void __launch_bounds__(256)
convert_x_xa_kernel(const float* __restrict__ x,
                    const void*  __restrict__ labels,
                    const float* __restrict__ A, int T) {
    int t = blockIdx.x * 8 + (threadIdx.x >> 5);
    if (t >= T) return;
    const int lane = threadIdx.x & 31;
    const int e = load_label(labels, t);
    const float* xrow = x + (size_t)t * D_DIM;
    const float* Ae   = A + (size_t)e * D_DIM * R_DIM;
    unsigned short* xo = g_x16 + (size_t)t * D_DIM;

    float acc[R_DIM];
#pragma unroll
    for (int r = 0; r < R_DIM; ++r) acc[r] = 0.0f;

#pragma unroll
    for (int i = 0; i < 8; ++i) {
        const int d = i * 128 + lane * 4;
        float4 v = *(const float4*)(xrow + d);
        float vv[4] = {v.x, v.y, v.z, v.w};

        ushort4 h4;
        __half h;
        h = __float2half_rn(vv[0]); h4.x = *(unsigned short*)&h;
        h = __float2half_rn(vv[1]); h4.y = *(unsigned short*)&h;
        h = __float2half_rn(vv[2]); h4.z = *(unsigned short*)&h;
        h = __float2half_rn(vv[3]); h4.w = *(unsigned short*)&h;
        *(ushort4*)(xo + d) = h4;

#pragma unroll
        for (int j = 0; j < 4; ++j) {
            const float4* ap = (const float4*)(Ae + (size_t)(d + j) * R_DIM);
            float4 a0 = ap[0], a1 = ap[1];
            float xv = vv[j];
            acc[0] += xv * a0.x;  acc[1] += xv * a0.y;
            acc[2] += xv * a0.z;  acc[3] += xv * a0.w;
            acc[4] += xv * a1.x;  acc[5] += xv * a1.y;
            acc[6] += xv * a1.z;  acc[7] += xv * a1.w;
        }
    }
#pragma unroll
    for (int off = 16; off > 0; off >>= 1)
#pragma unroll
        for (int r = 0; r < R_DIM; ++r)
            acc[r] += __shfl_down_sync(0xffffffffu, acc[r], off);
    if (lane == 0) {
        float4* o = (float4*)(g_xa + (size_t)t * R_DIM);
        o[0] = make_float4(acc[0], acc[1], acc[2], acc[3]);
        o[1] = make_float4(acc[4], acc[5], acc[6], acc[7]);
    }
}

// ---------------------------------------------------------------------------
// Kernel 2: Wt[n][k] = fp16(W[k][n])
// ---------------------------------------------------------------------------
__global__ void __launch_bounds__(256)
convert_w_kernel(const float* __restrict__ W) {
    __shared__ float s[32][33];
    const int k0 = blockIdx.x * 32;
    const int n0 = blockIdx.y * 32;
    const int tx = threadIdx.x & 31;
    const int ty = threadIdx.x >> 5;
#pragma unroll
    for (int r = 0; r < 4; ++r) {
        int kk = ty + r * 8;
        s[kk][tx] = W[(size_t)(k0 + kk) * D_DIM + n0 + tx];
    }
    __syncthreads();
#pragma unroll
    for (int r = 0; r < 4; ++r) {
        int nn = ty + r * 8;
        __half h = __float2half_rn(s[tx][nn]);
        g_w16[(size_t)(n0 + nn) * D_DIM + k0 + tx] = *(unsigned short*)&h;
    }
}

// ---------------------------------------------------------------------------
// Kernel 3: fp16 GEMM + fused LoRA/bias epilogue.
//   512 threads = 16 warps (4M x 4N), warp tile 32x32, BM=BN=128.
//   5-stage cp.async pipeline; prefetch (distance 4) issued before compute.
// ---------------------------------------------------------------------------
__global__ void __launch_bounds__(512, 1)
gemm_lora_kernel(const void*  __restrict__ labels,
                 const float* __restrict__ Bmat,
                 const float* __restrict__ bias,
                 float* __restrict__ out) {
    extern __shared__ char smem[];
    const uint32_t sbase = smem_u32(smem);
    const int tid  = threadIdx.x;
    const int row0 = blockIdx.y * BM;
    const int col0 = blockIdx.x * BN;

    // cp.async geometry: rows of 128B data split into 8x16B segments.
    // 512 threads cover 64 rows per pass; 2 passes per plane.
    const int lrow = tid >> 3;           // 0..63
    const int lseg = tid & 7;            // 16B segment within 128B row

    // warp/lane geometry: 4M x 4N warps, each 32x32
    const int warp = tid >> 5, lane = tid & 31;
    const int wm = warp >> 2, wn = warp & 3;
    const uint32_t a_lm_base =
        (uint32_t)((wm * 32 + (lane & 15)) * ROWSTRIDE + (lane >> 4) * 8) * 2;
    const uint32_t b_lm_base =
        (uint32_t)((wn * 32 + (lane >> 4) * 8 + (lane & 7)) * ROWSTRIDE +
                   ((lane >> 3) & 1) * 8) * 2;

    float c[2][4][4];
#pragma unroll
    for (int i = 0; i < 2; ++i)
#pragma unroll
        for (int j = 0; j < 4; ++j)
#pragma unroll
            for (int q = 0; q < 4; ++q) c[i][j][q] = 0.0f;

    auto issue = [&](int cn) {
        const int kk = cn * BKB;
        const uint32_t sa = sbase + (uint32_t)(cn % NSTAGE) * STAGE_BYTES;
#pragma unroll
        for (int h = 0; h < 2; ++h) {
            const int r = lrow + h * 64;
            const uint32_t doff = (uint32_t)(r * (ROWSTRIDE * 2) + lseg * 16);
            CP_ASYNC16(sa + OFF_X + doff,
                       g_x16 + (size_t)(row0 + r) * D_DIM + kk + lseg * 8);
            CP_ASYNC16(sa + OFF_W + doff,
                       g_w16 + (size_t)(col0 + r) * D_DIM + kk + lseg * 8);
        }
    };

    // prologue: fill 4 stages (prefetch distance 4)
#pragma unroll
    for (int cn = 0; cn < 4; ++cn) { issue(cn); CP_COMMIT(); }

    for (int ch = 0; ch < NCHUNK; ++ch) {
        CP_WAIT3();          // chunk ch's group complete (<=3 outstanding)
        __syncthreads();     // all warps done reading the stage being rewritten

        if (ch + 4 < NCHUNK) { issue(ch + 4); }
        CP_COMMIT();

        const uint32_t sa = sbase + (uint32_t)(ch % NSTAGE) * STAGE_BYTES;

#pragma unroll
        for (int ks = 0; ks < 4; ++ks) {
            // resident B fragments (8 regs)
            uint32_t bfr[4][2];
#pragma unroll
            for (int p = 0; p < 2; ++p) {
                uint32_t bo = b_lm_base + (uint32_t)(p * 16 * ROWSTRIDE + ks * 16) * 2;
                uint32_t r0, r1, r2, r3;
                LDSM4(r0, r1, r2, r3, sa + OFF_W + bo);
                bfr[2 * p][0] = r0;      bfr[2 * p][1] = r1;
                bfr[2 * p + 1][0] = r2;  bfr[2 * p + 1][1] = r3;
            }
            // A fragments (8 regs), then 8 MMAs hitting distinct accumulators
            uint32_t afr[2][4];
#pragma unroll
            for (int mf = 0; mf < 2; ++mf) {
                uint32_t ao = a_lm_base + (uint32_t)(mf * 16 * ROWSTRIDE + ks * 16) * 2;
                LDSM4(afr[mf][0], afr[mf][1], afr[mf][2], afr[mf][3], sa + OFF_X + ao);
            }
#pragma unroll
            for (int mf = 0; mf < 2; ++mf)
#pragma unroll
                for (int nf = 0; nf < 4; ++nf)
                    MMA16816F16(c[mf][nf], afr[mf], bfr[nf]);
        }
    }
    CP_WAIT0();
    __syncthreads();

    // ---- stage accumulators to smem (reuse pipeline smem) ----
    float* acc_s = (float*)smem;                 // [128][132]
    const int g = lane >> 2, q = lane & 3;
#pragma unroll
    for (int mf = 0; mf < 2; ++mf) {
        const int r1 = wm * 32 + mf * 16 + g;
#pragma unroll
        for (int nf = 0; nf < 4; ++nf) {
            const int cc = wn * 32 + nf * 8 + q * 2;
            *(float2*)&acc_s[r1 * 132 + cc]       = make_float2(c[mf][nf][0], c[mf][nf][1]);
            *(float2*)&acc_s[(r1 + 8) * 132 + cc] = make_float2(c[mf][nf][2], c[mf][nf][3]);
        }
    }
    __syncthreads();

    // ---- epilogue: per-token rank-8 LoRA + bias, vectorized ----
    const int lr   = tid >> 2;           // 0..127
    const int qcol = (tid & 3) * 32;     // 32-col quarter
    const int t    = row0 + lr;
    const int e    = load_label(labels, t);

    float xs[R_DIM];
    {
        const float4* p = (const float4*)(g_xa + (size_t)t * R_DIM);
        float4 a0 = p[0], a1 = p[1];
        xs[0] = SCALING * a0.x; xs[1] = SCALING * a0.y;
        xs[2] = SCALING * a0.z; xs[3] = SCALING * a0.w;
        xs[4] = SCALING * a1.x; xs[5] = SCALING * a1.y;
        xs[6] = SCALING * a1.z; xs[7] = SCALING * a1.w;
    }

    float res[32];
#pragma unroll
    for (int v = 0; v < 8; ++v)
        *(float4*)&res[v * 4] = *(const float4*)&acc_s[lr * 132 + qcol + v * 4];

    const float* Be = Bmat + (size_t)e * R_DIM * D_DIM + col0 + qcol;
#pragma unroll
    for (int r = 0; r < R_DIM; ++r) {
        const float4* bp = (const float4*)(Be + (size_t)r * D_DIM);
        const float xr = xs[r];
#pragma unroll
        for (int v = 0; v < 8; ++v) {
            float4 b4 = bp[v];
            res[v * 4 + 0] += xr * b4.x;
            res[v * 4 + 1] += xr * b4.y;
            res[v * 4 + 2] += xr * b4.z;
            res[v * 4 + 3] += xr * b4.w;
        }
    }
    const float4* bi = (const float4*)(bias + col0 + qcol);
    float* op = out + (size_t)t * D_DIM + col0 + qcol;
#pragma unroll
    for (int v = 0; v < 8; ++v) {
        float4 bv = bi[v];
        float4 o4 = make_float4(res[v * 4 + 0] + bv.x, res[v * 4 + 1] + bv.y,
                                res[v * 4 + 2] + bv.z, res[v * 4 + 3] + bv.w);
        ((float4*)op)[v] = o4;
    }
}

// ---------------------------------------------------------------------------
// kernel_launch — graph-capturable, allocation-free.
// Inputs: x, labels, W, A, B, bias
// ---------------------------------------------------------------------------
extern "C" void kernel_launch(void* const* d_in, const int* in_sizes, int n_in,
                              void* d_out, int out_size) {
    const float* x      = (const float*)d_in[0];
    const void*  labels = (const void*) d_in[1];
    const float* W      = (const float*)d_in[2];
    const float* A      = (const float*)d_in[3];
    const float* B      = (const float*)d_in[4];
    const float* bias   = (const float*)d_in[5];
    float* out          = (float*)d_out;

    const int T = in_sizes[0] / D_DIM;

    detect_label_dtype_kernel<<<1, 32>>>(labels, T);
    convert_x_xa_kernel<<<(T + 7) / 8, 256>>>(x, labels, A, T);
    convert_w_kernel<<<dim3(D_DIM / 32, D_DIM / 32), 256>>>(W);

    static int smem_set = 0;
    if (!smem_set) {
        cudaFuncSetAttribute(gemm_lora_kernel,
                             cudaFuncAttributeMaxDynamicSharedMemorySize, SMEM_BYTES);
        smem_set = 1;
    }
    dim3 grid(D_DIM / BN, T / BM);
    gemm_lora_kernel<<<grid, 512, SMEM_BYTES>>>(labels, B, bias, out);
}